// round 2
// baseline (speedup 1.0000x reference)
#include <cuda_runtime.h>
#include <math.h>

// Problem constants
#define NROWS 16384   // B*T
#define KCB   4096    // codebook size
#define DD    256     // feature dim
#define TOPK  3

// Output layout (flattened tuple, float32)
#define OFF_LOSS   0u
#define OFF_QUANT  1u                      // 16*1024*3*256 = 12,582,912
#define OFF_PERP   12582913u
#define OFF_AVGP   12582914u               // 4096
#define OFF_IDX    12587010u               // 49152
#define OFF_DIST   12636162u               // 67,108,864
#define OFF_NEWCS  79745026u               // 4096
#define OFF_EMAW   79749122u               // 1,048,576
#define OFF_UPD    80797698u               // 1,048,576
// total = 81,846,274

// Device scratch (no allocations allowed)
__device__ float g_xnorm[NROWS];
__device__ float g_enorm[KCB];
__device__ int   g_idx[NROWS * TOPK];
__device__ int   g_counts[KCB];
__device__ float g_loss;

// ---------------------------------------------------------------------------
// Kernel 0: norms + zero scratch + init new_ema_w = 0.99 * ema_w
// ---------------------------------------------------------------------------
__global__ void prep_kernel(const float* __restrict__ X,
                            const float* __restrict__ E,
                            const float* __restrict__ ema_w,
                            float* __restrict__ out_emaw) {
    int tid = blockIdx.x * blockDim.x + threadIdx.x;
    if (tid < KCB) g_counts[tid] = 0;
    if (tid == 0)  g_loss = 0.0f;

    int warp = tid >> 5;
    int lane = tid & 31;
    if (warp < NROWS + KCB) {
        const float* base = (warp < NROWS) ? (X + (size_t)warp * DD)
                                           : (E + (size_t)(warp - NROWS) * DD);
        float s = 0.0f;
        #pragma unroll
        for (int i = 0; i < DD / 32; i++) {
            float v = base[lane + i * 32];
            s += v * v;
        }
        #pragma unroll
        for (int o = 16; o > 0; o >>= 1) s += __shfl_xor_sync(0xffffffffu, s, o);
        if (lane == 0) {
            if (warp < NROWS) g_xnorm[warp] = s;
            else              g_enorm[warp - NROWS] = s;
        }
    }

    int stride = gridDim.x * blockDim.x;
    for (int i = tid; i < KCB * DD; i += stride)
        out_emaw[i] = 0.99f * ema_w[i];
}

// ---------------------------------------------------------------------------
// Kernel 1: fp32 SGEMM-style distance matrix
// dist[n,k] = ||x_n||^2 + ||e_k||^2 - 2 * <x_n, e_k>
// Block tile 64x64, thread tile 4x4, BK=16, 256 threads.
// ---------------------------------------------------------------------------
#define BM 64
#define BN 64
#define BKT 16

__global__ __launch_bounds__(256) void gemm_dist_kernel(
    const float* __restrict__ X, const float* __restrict__ E,
    float* __restrict__ dist) {
    __shared__ float As[BKT][BM + 4];  // +4 keeps 16B row alignment (68*4=272)
    __shared__ float Bs[BKT][BN + 4];

    int tid = threadIdx.x;
    int bx = blockIdx.x;  // column tile over K (codebook)
    int by = blockIdx.y;  // row tile over N (tokens)
    int tx = tid & 15;
    int ty = tid >> 4;

    float acc[4][4];
    #pragma unroll
    for (int i = 0; i < 4; i++)
        #pragma unroll
        for (int j = 0; j < 4; j++) acc[i][j] = 0.0f;

    int lr = tid >> 2;         // 0..63: row within tile
    int lc = (tid & 3) * 4;    // 0,4,8,12 within BK
    const float* Xb = X + ((size_t)(by * BM + lr)) * DD;
    const float* Eb = E + ((size_t)(bx * BN + lr)) * DD;

    for (int k0 = 0; k0 < DD; k0 += BKT) {
        float4 xa = *(const float4*)(Xb + k0 + lc);
        float4 ea = *(const float4*)(Eb + k0 + lc);
        As[lc + 0][lr] = xa.x; As[lc + 1][lr] = xa.y;
        As[lc + 2][lr] = xa.z; As[lc + 3][lr] = xa.w;
        Bs[lc + 0][lr] = ea.x; Bs[lc + 1][lr] = ea.y;
        Bs[lc + 2][lr] = ea.z; Bs[lc + 3][lr] = ea.w;
        __syncthreads();
        #pragma unroll
        for (int kk = 0; kk < BKT; kk++) {
            float a[4], b[4];
            *(float4*)a = *(const float4*)&As[kk][ty * 4];
            *(float4*)b = *(const float4*)&Bs[kk][tx * 4];
            #pragma unroll
            for (int i = 0; i < 4; i++)
                #pragma unroll
                for (int j = 0; j < 4; j++) acc[i][j] += a[i] * b[j];
        }
        __syncthreads();
    }

    #pragma unroll
    for (int i = 0; i < 4; i++) {
        int r = by * BM + ty * 4 + i;
        float xn = g_xnorm[r];
        #pragma unroll
        for (int j = 0; j < 4; j++) {
            int c = bx * BN + tx * 4 + j;
            dist[(size_t)r * KCB + c] = xn + g_enorm[c] - 2.0f * acc[i][j];
        }
    }
}

// ---------------------------------------------------------------------------
// Kernel 2: top-3 smallest per row (tie-break: smaller index wins,
// matching jax.lax.top_k on negated distances)
// ---------------------------------------------------------------------------
__device__ __forceinline__ void ins3(float d, int i,
                                     float& d0, int& i0,
                                     float& d1, int& i1,
                                     float& d2, int& i2) {
    if (d < d2 || (d == d2 && i < i2)) {
        if (d < d0 || (d == d0 && i < i0)) {
            d2 = d1; i2 = i1; d1 = d0; i1 = i0; d0 = d; i0 = i;
        } else if (d < d1 || (d == d1 && i < i1)) {
            d2 = d1; i2 = i1; d1 = d; i1 = i;
        } else {
            d2 = d; i2 = i;
        }
    }
}

__global__ __launch_bounds__(128) void top3_kernel(
    const float* __restrict__ dist, float* __restrict__ out_idx_f) {
    int n = blockIdx.x;
    const float* row = dist + (size_t)n * KCB;
    int tid = threadIdx.x;

    float d0 = 3.4e38f, d1 = 3.4e38f, d2 = 3.4e38f;
    int i0 = 0x7fffffff, i1 = 0x7fffffff, i2 = 0x7fffffff;

    for (int k = tid; k < KCB; k += 128) {
        float d = row[k];
        ins3(d, k, d0, i0, d1, i1, d2, i2);
    }
    // warp butterfly merge
    #pragma unroll
    for (int off = 16; off > 0; off >>= 1) {
        float rd0 = __shfl_xor_sync(0xffffffffu, d0, off);
        float rd1 = __shfl_xor_sync(0xffffffffu, d1, off);
        float rd2 = __shfl_xor_sync(0xffffffffu, d2, off);
        int ri0 = __shfl_xor_sync(0xffffffffu, i0, off);
        int ri1 = __shfl_xor_sync(0xffffffffu, i1, off);
        int ri2 = __shfl_xor_sync(0xffffffffu, i2, off);
        ins3(rd0, ri0, d0, i0, d1, i1, d2, i2);
        ins3(rd1, ri1, d0, i0, d1, i1, d2, i2);
        ins3(rd2, ri2, d0, i0, d1, i1, d2, i2);
    }
    __shared__ float sd[4][3];
    __shared__ int   si[4][3];
    int w = tid >> 5;
    if ((tid & 31) == 0) {
        sd[w][0] = d0; sd[w][1] = d1; sd[w][2] = d2;
        si[w][0] = i0; si[w][1] = i1; si[w][2] = i2;
    }
    __syncthreads();
    if (tid == 0) {
        float f0 = sd[0][0], f1 = sd[0][1], f2 = sd[0][2];
        int   j0 = si[0][0], j1 = si[0][1], j2 = si[0][2];
        #pragma unroll
        for (int ww = 1; ww < 4; ww++)
            #pragma unroll
            for (int c = 0; c < 3; c++)
                ins3(sd[ww][c], si[ww][c], f0, j0, f1, j1, f2, j2);
        g_idx[n * 3 + 0] = j0;
        g_idx[n * 3 + 1] = j1;
        g_idx[n * 3 + 2] = j2;
        out_idx_f[n * 3 + 0] = (float)j0;
        out_idx_f[n * 3 + 1] = (float)j1;
        out_idx_f[n * 3 + 2] = (float)j2;
    }
}

// ---------------------------------------------------------------------------
// Kernel 3: gather quant_st, loss partials, counts, EMA scatter-add
// One block per row (256 threads = D)
// ---------------------------------------------------------------------------
__global__ __launch_bounds__(256) void gather_kernel(
    const float* __restrict__ X, const float* __restrict__ E,
    float* __restrict__ out) {
    int n = blockIdx.x;
    int d = threadIdx.x;
    float xv = X[(size_t)n * DD + d];
    int ks0 = g_idx[n * 3 + 0];
    int ks1 = g_idx[n * 3 + 1];
    int ks2 = g_idx[n * 3 + 2];
    int ks[3] = {ks0, ks1, ks2};

    float sumsq = 0.0f;
    #pragma unroll
    for (int j = 0; j < 3; j++) {
        int k = ks[j];
        float ev = E[(size_t)k * DD + d];
        out[OFF_QUANT + ((size_t)n * 3 + j) * DD + d] = ev;
        float diff = ev - xv;
        sumsq += diff * diff;
        atomicAdd(&out[OFF_EMAW + (size_t)k * DD + d], 0.01f * xv);
    }
    if (d < 3) atomicAdd(&g_counts[ks[d]], 1);

    // block reduce sumsq
    #pragma unroll
    for (int o = 16; o > 0; o >>= 1) sumsq += __shfl_xor_sync(0xffffffffu, sumsq, o);
    __shared__ float red[8];
    if ((d & 31) == 0) red[d >> 5] = sumsq;
    __syncthreads();
    if (d == 0) {
        float t = 0.0f;
        #pragma unroll
        for (int i = 0; i < 8; i++) t += red[i];
        atomicAdd(&g_loss, t);
    }
}

// ---------------------------------------------------------------------------
// Kernel 4: new_cs, avg_probs, perplexity, loss (single block, 1024 threads)
// ---------------------------------------------------------------------------
__global__ __launch_bounds__(1024) void finalize_kernel(
    const float* __restrict__ ema_cs, float* __restrict__ out) {
    int tid = threadIdx.x;
    float nsum = 0.0f, plp = 0.0f;
    for (int k = tid; k < KCB; k += 1024) {
        float pre = ema_cs[k] * 0.99f + 0.01f * (float)g_counts[k];
        nsum += pre;
        float p = (float)g_counts[k] * (1.0f / 16384.0f);
        plp += p * logf(p + 1e-10f);
    }
    __shared__ float sN[32], sP[32];
    #pragma unroll
    for (int o = 16; o > 0; o >>= 1) {
        nsum += __shfl_xor_sync(0xffffffffu, nsum, o);
        plp  += __shfl_xor_sync(0xffffffffu, plp, o);
    }
    if ((tid & 31) == 0) { sN[tid >> 5] = nsum; sP[tid >> 5] = plp; }
    __syncthreads();
    if (tid < 32) {
        float a = sN[tid], b = sP[tid];
        #pragma unroll
        for (int o = 16; o > 0; o >>= 1) {
            a += __shfl_xor_sync(0xffffffffu, a, o);
            b += __shfl_xor_sync(0xffffffffu, b, o);
        }
        if (tid == 0) { sN[0] = a; sP[0] = b; }
    }
    __syncthreads();
    float nfin = sN[0];
    float plpt = sP[0];
    float scale = nfin / (nfin + (float)KCB * 1e-5f);
    for (int k = tid; k < KCB; k += 1024) {
        float pre = ema_cs[k] * 0.99f + 0.01f * (float)g_counts[k];
        out[OFF_NEWCS + k] = (pre + 1e-5f) * scale;
        out[OFF_AVGP + k] = (float)g_counts[k] * (1.0f / 16384.0f);
    }
    if (tid == 0) {
        out[OFF_LOSS] = 0.25f * g_loss * (1.0f / (16384.0f * 3.0f * 256.0f));
        out[OFF_PERP] = expf(-plpt);
    }
}

// ---------------------------------------------------------------------------
// Kernel 5: updated_embeddings = new_ema_w / new_cs
// ---------------------------------------------------------------------------
__global__ __launch_bounds__(256) void upd_kernel(float* __restrict__ out) {
    int t = blockIdx.x * blockDim.x + threadIdx.x;
    if (t < KCB * DD)
        out[OFF_UPD + t] = out[OFF_EMAW + t] / out[OFF_NEWCS + (t >> 8)];
}

// ---------------------------------------------------------------------------
extern "C" void kernel_launch(void* const* d_in, const int* in_sizes, int n_in,
                              void* d_out, int out_size) {
    const float* X      = (const float*)d_in[0];  // [16,1024,256]
    const float* E      = (const float*)d_in[1];  // [4096,256]
    const float* ema_cs = (const float*)d_in[2];  // [4096]
    const float* ema_w  = (const float*)d_in[3];  // [4096,256]
    float* out = (float*)d_out;

    (void)in_sizes; (void)n_in; (void)out_size;

    // warps needed: 16384 + 4096 = 20480 -> 2560 blocks of 256
    prep_kernel<<<2560, 256>>>(X, E, ema_w, out + OFF_EMAW);

    dim3 ggrid(KCB / BN, NROWS / BM);  // (64, 256)
    gemm_dist_kernel<<<ggrid, 256>>>(X, E, out + OFF_DIST);

    top3_kernel<<<NROWS, 128>>>(out + OFF_DIST, out + OFF_IDX);

    gather_kernel<<<NROWS, 256>>>(X, E, out);

    finalize_kernel<<<1, 1024>>>(ema_cs, out);

    upd_kernel<<<(KCB * DD + 255) / 256, 256>>>(out);
}

// round 5
// speedup vs baseline: 2.3344x; 2.3344x over previous
#include <cuda_runtime.h>
#include <cuda_fp16.h>
#include <stdint.h>
#include <math.h>

// Problem constants
#define NROWS 16384   // B*T
#define KCB   4096    // codebook size
#define DD    256     // feature dim
#define TOPK  3

// Output layout (flattened tuple, float32)
#define OFF_LOSS   0u
#define OFF_QUANT  1u
#define OFF_PERP   12582913u
#define OFF_AVGP   12582914u
#define OFF_IDX    12587010u
#define OFF_DIST   12636162u
#define OFF_NEWCS  79745026u
#define OFF_EMAW   79749122u
#define OFF_UPD    80797698u

// Device scratch (no allocations allowed)
__device__ float g_xnorm[NROWS];
__device__ float g_enorm[KCB];
__device__ int   g_idx[NROWS * TOPK];
__device__ int   g_counts[KCB];
__device__ float g_loss;

// fp16 copies for tensor-core GEMM
__device__ __align__(128) __half g_xh[NROWS * DD];
__device__ __align__(128) __half g_eh[KCB * DD];

// ---------------------------------------------------------------------------
// PTX helpers
// ---------------------------------------------------------------------------
__device__ __forceinline__ uint32_t smem_u32(const void* p) {
    uint32_t a;
    asm("{ .reg .u64 t; cvta.to.shared.u64 t, %1; cvt.u32.u64 %0, t; }"
        : "=r"(a) : "l"(p));
    return a;
}
__device__ __forceinline__ void cp16(uint32_t dst, const void* src) {
    asm volatile("cp.async.cg.shared.global [%0], [%1], 16;"
                 :: "r"(dst), "l"(src) : "memory");
}
__device__ __forceinline__ void cp_commit() {
    asm volatile("cp.async.commit_group;" ::: "memory");
}
template <int N>
__device__ __forceinline__ void cp_wait() {
    asm volatile("cp.async.wait_group %0;" :: "n"(N) : "memory");
}
__device__ __forceinline__ void ldm_x4(uint32_t* r, uint32_t addr) {
    asm volatile("ldmatrix.sync.aligned.m8n8.x4.shared.b16 {%0,%1,%2,%3}, [%4];"
                 : "=r"(r[0]), "=r"(r[1]), "=r"(r[2]), "=r"(r[3]) : "r"(addr));
}
__device__ __forceinline__ void ldm_x2(uint32_t* r, uint32_t addr) {
    asm volatile("ldmatrix.sync.aligned.m8n8.x2.shared.b16 {%0,%1}, [%2];"
                 : "=r"(r[0]), "=r"(r[1]) : "r"(addr));
}
__device__ __forceinline__ void mma16816(float* c, const uint32_t* a, const uint32_t* b) {
    asm volatile(
        "mma.sync.aligned.m16n8k16.row.col.f32.f16.f16.f32 "
        "{%0,%1,%2,%3}, {%4,%5,%6,%7}, {%8,%9}, {%0,%1,%2,%3};"
        : "+f"(c[0]), "+f"(c[1]), "+f"(c[2]), "+f"(c[3])
        : "r"(a[0]), "r"(a[1]), "r"(a[2]), "r"(a[3]), "r"(b[0]), "r"(b[1]));
}

// ---------------------------------------------------------------------------
// Kernel 0: norms + zero scratch + fp16 conversion + new_ema_w init
// ---------------------------------------------------------------------------
__global__ void prep_kernel(const float* __restrict__ X,
                            const float* __restrict__ E,
                            const float* __restrict__ ema_w,
                            float* __restrict__ out_emaw) {
    int tid = blockIdx.x * blockDim.x + threadIdx.x;
    int stride = gridDim.x * blockDim.x;
    if (tid < KCB) g_counts[tid] = 0;
    if (tid == 0)  g_loss = 0.0f;

    int warp = tid >> 5;
    int lane = tid & 31;
    if (warp < NROWS + KCB) {
        const float* base = (warp < NROWS) ? (X + (size_t)warp * DD)
                                           : (E + (size_t)(warp - NROWS) * DD);
        float s = 0.0f;
        #pragma unroll
        for (int i = 0; i < DD / 32; i++) {
            float v = base[lane + i * 32];
            s += v * v;
        }
        #pragma unroll
        for (int o = 16; o > 0; o >>= 1) s += __shfl_xor_sync(0xffffffffu, s, o);
        if (lane == 0) {
            if (warp < NROWS) g_xnorm[warp] = s;
            else              g_enorm[warp - NROWS] = s;
        }
    }

    for (int i = tid; i < NROWS * DD; i += stride)
        g_xh[i] = __float2half(X[i]);
    for (int i = tid; i < KCB * DD; i += stride)
        g_eh[i] = __float2half(E[i]);
    for (int i = tid; i < KCB * DD; i += stride)
        out_emaw[i] = 0.99f * ema_w[i];
}

// ---------------------------------------------------------------------------
// Kernel 1: HMMA fp16 distance GEMM
// CTA tile 128(M tokens) x 128(N codebook), BK=64, 2-stage cp.async pipeline
// 8 warps in 2x4 grid -> 64x32 warp tiles -> m16n8k16 frags
// ---------------------------------------------------------------------------
#define BM 128
#define BN 128
#define BK 64
#define STAGE_A 16384            // 128 rows * 128 bytes
#define SMEM_GEMM (4 * 16384)    // A[2] + B[2]

__device__ __forceinline__ void load_stage(int stage, int k0, int tid,
                                           int mrow0, int nrow0, uint32_t smb) {
    const __half* ga = g_xh + (size_t)mrow0 * DD + k0;
    const __half* gb = g_eh + (size_t)nrow0 * DD + k0;
    uint32_t abase = smb + stage * STAGE_A;
    uint32_t bbase = smb + 32768 + stage * STAGE_A;
    #pragma unroll
    for (int i = 0; i < 4; i++) {
        int u = tid + i * 256;         // 0..1023 : 128 rows x 8 16B-units
        int row = u >> 3, c8 = u & 7;
        uint32_t sw = (uint32_t)((c8 ^ (row & 7)) << 4);
        cp16(abase + row * 128 + sw, ga + (size_t)row * DD + c8 * 8);
        cp16(bbase + row * 128 + sw, gb + (size_t)row * DD + c8 * 8);
    }
    cp_commit();
}

__global__ __launch_bounds__(256, 2) void gemm_dist_kernel(float* __restrict__ dist) {
    extern __shared__ char smem[];
    uint32_t smb = smem_u32(smem);
    int tid = threadIdx.x;
    int wid = tid >> 5;
    int lane = tid & 31;
    int warp_m = wid >> 2;           // 0-1 -> 64-row slab
    int warp_n = wid & 3;            // 0-3 -> 32-col slab
    int mrow0 = blockIdx.y * BM;
    int nrow0 = blockIdx.x * BN;

    float acc[4][4][4];
    #pragma unroll
    for (int i = 0; i < 4; i++)
        #pragma unroll
        for (int j = 0; j < 4; j++)
            #pragma unroll
            for (int t = 0; t < 4; t++) acc[i][j][t] = 0.0f;

    load_stage(0, 0, tid, mrow0, nrow0, smb);
    load_stage(1, BK, tid, mrow0, nrow0, smb);

    #pragma unroll
    for (int kt = 0; kt < 4; kt++) {
        if (kt < 3) cp_wait<1>(); else cp_wait<0>();
        __syncthreads();

        uint32_t a_s = smb + (kt & 1) * STAGE_A;
        uint32_t b_s = smb + 32768 + (kt & 1) * STAGE_A;
        #pragma unroll
        for (int ks = 0; ks < 4; ks++) {
            uint32_t a[4][4], b[4][2];
            int arow = warp_m * 64 + (lane & 15);
            int ac8 = ks * 2 + (lane >> 4);
            #pragma unroll
            for (int i = 0; i < 4; i++) {
                int r = arow + i * 16;
                ldm_x4(a[i], a_s + r * 128 + ((ac8 ^ (r & 7)) << 4));
            }
            int brow = warp_n * 32 + (lane & 7);
            int bc8 = ks * 2 + ((lane >> 3) & 1);
            #pragma unroll
            for (int j = 0; j < 4; j++) {
                int r = brow + j * 8;
                ldm_x2(b[j], b_s + r * 128 + ((bc8 ^ (r & 7)) << 4));
            }
            #pragma unroll
            for (int i = 0; i < 4; i++)
                #pragma unroll
                for (int j = 0; j < 4; j++)
                    mma16816(acc[i][j], a[i], b[j]);
        }
        __syncthreads();
        if (kt + 2 < 4) load_stage(kt & 1, (kt + 2) * BK, tid, mrow0, nrow0, smb);
    }

    // epilogue: dist = xn + en - 2*dot
    float* en_s = (float*)smem;
    for (int i = tid; i < BN; i += 256) en_s[i] = g_enorm[nrow0 + i];
    __syncthreads();

    #pragma unroll
    for (int i = 0; i < 4; i++) {
        int r_loc = warp_m * 64 + i * 16 + (lane >> 2);
        int r0 = mrow0 + r_loc;
        int r1 = r0 + 8;
        float xn0 = g_xnorm[r0];
        float xn1 = g_xnorm[r1];
        #pragma unroll
        for (int j = 0; j < 4; j++) {
            int c_loc = warp_n * 32 + j * 8 + (lane & 3) * 2;
            float en0 = en_s[c_loc], en1 = en_s[c_loc + 1];
            float2 v0 = make_float2(xn0 + en0 - 2.0f * acc[i][j][0],
                                    xn0 + en1 - 2.0f * acc[i][j][1]);
            float2 v1 = make_float2(xn1 + en0 - 2.0f * acc[i][j][2],
                                    xn1 + en1 - 2.0f * acc[i][j][3]);
            *(float2*)(dist + (size_t)r0 * KCB + nrow0 + c_loc) = v0;
            *(float2*)(dist + (size_t)r1 * KCB + nrow0 + c_loc) = v1;
        }
    }
}

// ---------------------------------------------------------------------------
// Kernel 2: approximate top-6 per row, exact fp32 refine -> top-3
// ---------------------------------------------------------------------------
#define NCAND 6

__device__ __forceinline__ void ins6(float v, int k, float* bd, int* bi) {
    #pragma unroll
    for (int j = 0; j < NCAND; j++) {
        if (v < bd[j] || (v == bd[j] && k < bi[j])) {
            float tv = bd[j]; bd[j] = v; v = tv;
            int   tk = bi[j]; bi[j] = k; k = tk;
        }
    }
}

__global__ __launch_bounds__(128) void topk_kernel(
    const float* __restrict__ dist, const float* __restrict__ X,
    const float* __restrict__ E, float* __restrict__ out_idx_f) {
    int n = blockIdx.x;
    const float* row = dist + (size_t)n * KCB;
    int tid = threadIdx.x;
    int w = tid >> 5, lane = tid & 31;

    float bd[NCAND];
    int   bi[NCAND];
    #pragma unroll
    for (int j = 0; j < NCAND; j++) { bd[j] = 3.4e38f; bi[j] = 0x7fffffff; }

    #pragma unroll 4
    for (int k = tid; k < KCB; k += 128)
        ins6(row[k], k, bd, bi);

    // warp butterfly merge
    #pragma unroll
    for (int off = 16; off > 0; off >>= 1) {
        float rd[NCAND]; int ri[NCAND];
        #pragma unroll
        for (int j = 0; j < NCAND; j++) {
            rd[j] = __shfl_xor_sync(0xffffffffu, bd[j], off);
            ri[j] = __shfl_xor_sync(0xffffffffu, bi[j], off);
        }
        #pragma unroll
        for (int j = 0; j < NCAND; j++) ins6(rd[j], ri[j], bd, bi);
    }

    __shared__ float sd[4][NCAND];
    __shared__ int   si[4][NCAND];
    __shared__ int   cand[NCAND];
    __shared__ float cdist[NCAND];
    if (lane == 0) {
        #pragma unroll
        for (int j = 0; j < NCAND; j++) { sd[w][j] = bd[j]; si[w][j] = bi[j]; }
    }
    __syncthreads();
    if (tid == 0) {
        float md[NCAND]; int mi[NCAND];
        #pragma unroll
        for (int j = 0; j < NCAND; j++) { md[j] = sd[0][j]; mi[j] = si[0][j]; }
        for (int ww = 1; ww < 4; ww++)
            #pragma unroll
            for (int j = 0; j < NCAND; j++) ins6(sd[ww][j], si[ww][j], md, mi);
        #pragma unroll
        for (int j = 0; j < NCAND; j++) cand[j] = mi[j];
    }
    __syncthreads();

    // exact fp32 recompute for the 6 candidates
    const float* xr = X + (size_t)n * DD;
    for (int c = w; c < NCAND; c += 4) {
        int k = cand[c];
        const float* er = E + (size_t)k * DD;
        float dot = 0.0f;
        #pragma unroll
        for (int j = 0; j < 8; j++)
            dot += xr[lane + j * 32] * er[lane + j * 32];
        #pragma unroll
        for (int o = 16; o > 0; o >>= 1) dot += __shfl_xor_sync(0xffffffffu, dot, o);
        if (lane == 0)
            cdist[c] = g_xnorm[n] + g_enorm[k] - 2.0f * dot;
    }
    __syncthreads();

    if (tid == 0) {
        float d[NCAND]; int ix[NCAND];
        #pragma unroll
        for (int j = 0; j < NCAND; j++) { d[j] = cdist[j]; ix[j] = cand[j]; }
        // selection sort the first 3 by (dist, idx)
        #pragma unroll
        for (int t = 0; t < TOPK; t++) {
            int best = t;
            #pragma unroll
            for (int j = 0; j < NCAND; j++) {
                if (j > t && (d[j] < d[best] || (d[j] == d[best] && ix[j] < ix[best])))
                    best = j;
            }
            float td = d[t]; d[t] = d[best]; d[best] = td;
            int ti = ix[t]; ix[t] = ix[best]; ix[best] = ti;
            g_idx[n * TOPK + t] = ix[t];
            out_idx_f[n * TOPK + t] = (float)ix[t];
        }
    }
}

// ---------------------------------------------------------------------------
// Kernel 3: gather quant_st, loss partials, counts, EMA scatter-add
// ---------------------------------------------------------------------------
__global__ __launch_bounds__(256) void gather_kernel(
    const float* __restrict__ X, const float* __restrict__ E,
    float* __restrict__ out) {
    int n = blockIdx.x;
    int d = threadIdx.x;
    float xv = X[(size_t)n * DD + d];
    int ks[3] = {g_idx[n * 3 + 0], g_idx[n * 3 + 1], g_idx[n * 3 + 2]};

    float sumsq = 0.0f;
    #pragma unroll
    for (int j = 0; j < 3; j++) {
        int k = ks[j];
        float ev = E[(size_t)k * DD + d];
        out[OFF_QUANT + ((size_t)n * 3 + j) * DD + d] = ev;
        float diff = ev - xv;
        sumsq += diff * diff;
        atomicAdd(&out[OFF_EMAW + (size_t)k * DD + d], 0.01f * xv);
    }
    if (d < 3) atomicAdd(&g_counts[ks[d]], 1);

    #pragma unroll
    for (int o = 16; o > 0; o >>= 1) sumsq += __shfl_xor_sync(0xffffffffu, sumsq, o);
    __shared__ float red[8];
    if ((d & 31) == 0) red[d >> 5] = sumsq;
    __syncthreads();
    if (d == 0) {
        float t = 0.0f;
        #pragma unroll
        for (int i = 0; i < 8; i++) t += red[i];
        atomicAdd(&g_loss, t);
    }
}

// ---------------------------------------------------------------------------
// Kernel 4: new_cs, avg_probs, perplexity, loss
// ---------------------------------------------------------------------------
__global__ __launch_bounds__(1024) void finalize_kernel(
    const float* __restrict__ ema_cs, float* __restrict__ out) {
    int tid = threadIdx.x;
    float nsum = 0.0f, plp = 0.0f;
    for (int k = tid; k < KCB; k += 1024) {
        float pre = ema_cs[k] * 0.99f + 0.01f * (float)g_counts[k];
        nsum += pre;
        float p = (float)g_counts[k] * (1.0f / 16384.0f);
        plp += p * logf(p + 1e-10f);
    }
    __shared__ float sN[32], sP[32];
    #pragma unroll
    for (int o = 16; o > 0; o >>= 1) {
        nsum += __shfl_xor_sync(0xffffffffu, nsum, o);
        plp  += __shfl_xor_sync(0xffffffffu, plp, o);
    }
    if ((tid & 31) == 0) { sN[tid >> 5] = nsum; sP[tid >> 5] = plp; }
    __syncthreads();
    if (tid < 32) {
        float a = sN[tid], b = sP[tid];
        #pragma unroll
        for (int o = 16; o > 0; o >>= 1) {
            a += __shfl_xor_sync(0xffffffffu, a, o);
            b += __shfl_xor_sync(0xffffffffu, b, o);
        }
        if (tid == 0) { sN[0] = a; sP[0] = b; }
    }
    __syncthreads();
    float nfin = sN[0];
    float plpt = sP[0];
    float scale = nfin / (nfin + (float)KCB * 1e-5f);
    for (int k = tid; k < KCB; k += 1024) {
        float pre = ema_cs[k] * 0.99f + 0.01f * (float)g_counts[k];
        out[OFF_NEWCS + k] = (pre + 1e-5f) * scale;
        out[OFF_AVGP + k] = (float)g_counts[k] * (1.0f / 16384.0f);
    }
    if (tid == 0) {
        out[OFF_LOSS] = 0.25f * g_loss * (1.0f / (16384.0f * 3.0f * 256.0f));
        out[OFF_PERP] = expf(-plpt);
    }
}

// ---------------------------------------------------------------------------
// Kernel 5: updated_embeddings = new_ema_w / new_cs
// ---------------------------------------------------------------------------
__global__ __launch_bounds__(256) void upd_kernel(float* __restrict__ out) {
    int t = blockIdx.x * blockDim.x + threadIdx.x;
    if (t < KCB * DD)
        out[OFF_UPD + t] = out[OFF_EMAW + t] / out[OFF_NEWCS + (t >> 8)];
}

// ---------------------------------------------------------------------------
extern "C" void kernel_launch(void* const* d_in, const int* in_sizes, int n_in,
                              void* d_out, int out_size) {
    const float* X      = (const float*)d_in[0];
    const float* E      = (const float*)d_in[1];
    const float* ema_cs = (const float*)d_in[2];
    const float* ema_w  = (const float*)d_in[3];
    float* out = (float*)d_out;
    (void)in_sizes; (void)n_in; (void)out_size;

    cudaFuncSetAttribute(gemm_dist_kernel,
                         cudaFuncAttributeMaxDynamicSharedMemorySize, SMEM_GEMM);

    prep_kernel<<<2560, 256>>>(X, E, ema_w, out + OFF_EMAW);

    dim3 ggrid(KCB / BN, NROWS / BM);  // (32, 128)
    gemm_dist_kernel<<<ggrid, 256, SMEM_GEMM>>>(out + OFF_DIST);

    topk_kernel<<<NROWS, 128>>>(out + OFF_DIST, X, E, out + OFF_IDX);

    gather_kernel<<<NROWS, 256>>>(X, E, out);

    finalize_kernel<<<1, 1024>>>(ema_cs, out);

    upd_kernel<<<(KCB * DD + 255) / 256, 256>>>(out);
}